// round 16
// baseline (speedup 1.0000x reference)
#include <cuda_runtime.h>
#include <cuda_fp16.h>
#include <math.h>
#include <stdint.h>

#define B_SZ  4
#define S_LEN 2048
#define D_DIM 1024
#define M_ROWS (B_SZ * S_LEN)   // 8192
#define NTILES (S_LEN / 128)    // 16

// ---------------- scratch (allocation-free: __device__ globals) ----------------
__device__ __half g_X16[(size_t)M_ROWS * D_DIM];              // fp16(x)
__device__ __half g_W16[(size_t)3 * D_DIM * D_DIM];           // fp16(wq|wk|wv) [3072][1024]
__device__ __half g_Q16[(size_t)M_ROWS * D_DIM];              // fp16 post-rope
__device__ __half g_K16[(size_t)M_ROWS * D_DIM];
__device__ __half g_V16[(size_t)M_ROWS * D_DIM];              // row-major [b*S+s][d]
__device__ __half g_P16[(size_t)B_SZ * S_LEN * S_LEN];        // fp16 exp(s - m_tile) -> probs
__device__ float2 g_stats[(size_t)M_ROWS * NTILES];           // per (qrow, ktile): (m_t, sum_t)

// ======================= helpers =======================
__device__ __forceinline__ uint32_t smem_u32(const void* p) {
    uint32_t a;
    asm("{ .reg .u64 t; cvta.to.shared.u64 t, %1; cvt.u32.u64 %0, t; }" : "=r"(a) : "l"(p));
    return a;
}
__device__ __forceinline__ uint32_t pack_h2(float a, float b) {
    __half2 h = __floats2half2_rn(a, b);
    return *(uint32_t*)&h;
}
__device__ __forceinline__ void ldsm4(uint32_t& r0, uint32_t& r1, uint32_t& r2, uint32_t& r3,
                                      uint32_t addr) {
    asm volatile("ldmatrix.sync.aligned.m8n8.x4.shared.b16 {%0,%1,%2,%3}, [%4];"
                 : "=r"(r0), "=r"(r1), "=r"(r2), "=r"(r3) : "r"(addr));
}
__device__ __forceinline__ void ldsm4t(uint32_t& r0, uint32_t& r1, uint32_t& r2, uint32_t& r3,
                                       uint32_t addr) {
    asm volatile("ldmatrix.sync.aligned.m8n8.x4.trans.shared.b16 {%0,%1,%2,%3}, [%4];"
                 : "=r"(r0), "=r"(r1), "=r"(r2), "=r"(r3) : "r"(addr));
}
__device__ __forceinline__ void mma16816(float& d0, float& d1, float& d2, float& d3,
                                         uint32_t a0, uint32_t a1, uint32_t a2, uint32_t a3,
                                         uint32_t b0, uint32_t b1) {
    asm volatile(
        "mma.sync.aligned.m16n8k16.row.col.f32.f16.f16.f32 "
        "{%0,%1,%2,%3},{%4,%5,%6,%7},{%8,%9},{%0,%1,%2,%3};"
        : "+f"(d0), "+f"(d1), "+f"(d2), "+f"(d3)
        : "r"(a0), "r"(a1), "r"(a2), "r"(a3), "r"(b0), "r"(b1));
}
__device__ __forceinline__ void cp16(uint32_t dst, const void* src) {
    asm volatile("cp.async.cg.shared.global [%0], [%1], 16;"
                 :: "r"(dst), "l"(__cvta_generic_to_global(src)) : "memory");
}
#define CP_COMMIT() asm volatile("cp.async.commit_group;" ::: "memory")
#define CP_WAIT2()  asm volatile("cp.async.wait_group 2;" ::: "memory")

// A / NT-B tiles: [128 rows][64 fp16] = 128B rows, 8x 16B chunks; phys chunk = ch ^ (row&7)
__device__ __forceinline__ uint32_t swp(int row, int chunk) {
    return (uint32_t)(row * 128 + ((chunk ^ (row & 7)) << 4));
}
// NN-B tile: [64 k-rows][128 n-cols] fp16 = 256B rows; chunk c(0..15) ^= k&7
__device__ __forceinline__ uint32_t swb(int k, int chunk) {
    return (uint32_t)(k * 256 + ((chunk ^ (k & 7)) << 4));
}

// CTA tile 128x128, BK=64, 8 warps (2x4), warp tile 64x32, 2 CTAs/SM
#define TILE_HB 16384
#define STAGE_BYTES (2 * TILE_HB)
#define SMEM_GEMM_BYTES (3 * STAGE_BYTES)   // 98304

// ======================= shared mainloop (round-11 proven: two-sync, WAIT2) =======================
template<int BMODE>
__device__ __forceinline__ void issue_stage(
    uint32_t base, const __half* Ag, const __half* Bg, int K, int ldB, int tid, int c)
{
    const __half* Ac = Ag + (long long)c * 64;
    #pragma unroll
    for (int p = 0; p < 4; p++) {
        int cidx = tid + p * 256;
        int row = cidx >> 3, ch = cidx & 7;
        cp16(base + swp(row, ch), Ac + (long long)row * K + ch * 8);
    }
    if (BMODE == 0) {
        const __half* Bc = Bg + (long long)c * 64;
        #pragma unroll
        for (int p = 0; p < 4; p++) {
            int cidx = tid + p * 256;
            int row = cidx >> 3, ch = cidx & 7;
            cp16(base + TILE_HB + swp(row, ch), Bc + (long long)row * K + ch * 8);
        }
    } else {
        const __half* Bc = Bg + (long long)c * 64 * ldB;
        #pragma unroll
        for (int p = 0; p < 4; p++) {
            int cidx = tid + p * 256;
            int k = cidx >> 4, ch = cidx & 15;
            cp16(base + TILE_HB + swb(k, ch), Bc + (long long)k * ldB + ch * 8);
        }
    }
    CP_COMMIT();
}

template<int BMODE>
__device__ __forceinline__ void gemm_mainloop(
    const __half* Ag, const __half* Bg, int K, int ldB,
    uint32_t sbase, int tid, float acc[4][4][4])
{
    const int wid = tid >> 5, lane = tid & 31;
    const int warpM = (wid >> 2) * 64, warpN = (wid & 3) * 32;
    const int NC = K >> 6;

    issue_stage<BMODE>(sbase,               Ag, Bg, K, ldB, tid, 0);
    issue_stage<BMODE>(sbase + STAGE_BYTES, Ag, Bg, K, ldB, tid, 1);

    const int laA = lane & 15, lcA = lane >> 4;
    const int laB = (lane & 7) + ((lane & 16) >> 1);
    const int lcB = (lane >> 3) & 1;
    const int lrT = lane & 7, gT = lane >> 3;

    for (int c = 0; c < NC; c++) {
        if (c + 2 < NC) {
            issue_stage<BMODE>(sbase + ((c + 2) % 3) * STAGE_BYTES, Ag, Bg, K, ldB, tid, c + 2);
        } else {
            CP_COMMIT();
        }
        CP_WAIT2();
        __syncthreads();

        const uint32_t sA = sbase + (c % 3) * STAGE_BYTES;
        const uint32_t sB = sA + TILE_HB;

        #pragma unroll
        for (int kk = 0; kk < 4; kk++) {
            uint32_t b[4][2];
            if (BMODE == 0) {
                #pragma unroll
                for (int g = 0; g < 2; g++) {
                    int rB = warpN + g * 16 + laB;
                    uint32_t off = swp(rB, 2 * kk + lcB);
                    ldsm4(b[2*g][0], b[2*g][1], b[2*g+1][0], b[2*g+1][1], sB + off);
                }
            } else {
                int k = kk * 16 + (gT & 1) * 8 + lrT;
                int cb = (warpN >> 3) + (gT >> 1);
                ldsm4t(b[0][0], b[0][1], b[1][0], b[1][1], sB + swb(k, cb));
                ldsm4t(b[2][0], b[2][1], b[3][0], b[3][1], sB + swb(k, cb + 2));
            }
            #pragma unroll
            for (int mt = 0; mt < 4; mt++) {
                int rA = warpM + mt * 16 + laA;
                uint32_t off = swp(rA, 2 * kk + lcA);
                uint32_t a0, a1, a2, a3;
                ldsm4(a0, a1, a2, a3, sA + off);
                #pragma unroll
                for (int nt = 0; nt < 4; nt++)
                    mma16816(acc[mt][nt][0], acc[mt][nt][1], acc[mt][nt][2], acc[mt][nt][3],
                             a0, a1, a2, a3, b[nt][0], b[nt][1]);
            }
        }
        __syncthreads();
    }
}

// ======================= PV GEMM (NN via ldmatrix.trans) =======================
__global__ void __launch_bounds__(256, 2) gemm_pv(
    const __half* __restrict__ A, const __half* __restrict__ B,
    float* __restrict__ C, int N, int K,
    long long sA, long long sB, long long sC)
{
    extern __shared__ uint32_t sm[];
    const uint32_t sbase = smem_u32(sm);
    const int tid = threadIdx.x, wid = tid >> 5, lane = tid & 31;
    const int bm = blockIdx.y * 128, bn = blockIdx.x * 128;

    const __half* Ag = A + blockIdx.z * sA + (long long)bm * K;
    const __half* Bg = B + blockIdx.z * sB + bn;

    float acc[4][4][4];
    #pragma unroll
    for (int m = 0; m < 4; m++)
        #pragma unroll
        for (int n = 0; n < 4; n++)
            #pragma unroll
            for (int e = 0; e < 4; e++) acc[m][n][e] = 0.0f;

    gemm_mainloop<1>(Ag, Bg, K, N, sbase, tid, acc);

    C += blockIdx.z * sC;
    const int warpM = (wid >> 2) * 64, warpN = (wid & 3) * 32;
    const int r = lane >> 2, q = lane & 3;
    #pragma unroll
    for (int mt = 0; mt < 4; mt++) {
        #pragma unroll
        for (int nt = 0; nt < 4; nt++) {
            int row = bm + warpM + mt * 16 + r;
            int col = bn + warpN + nt * 8 + q * 2;
            *(float2*)(C + (long long)row * N + col)       = make_float2(acc[mt][nt][0], acc[mt][nt][1]);
            *(float2*)(C + (long long)(row + 8) * N + col) = make_float2(acc[mt][nt][2], acc[mt][nt][3]);
        }
    }
}

// ======================= scores GEMM + tile softmax stats -> P16, stats =======================
__global__ void __launch_bounds__(256, 2) gemm_scores(
    const __half* __restrict__ Qm, const __half* __restrict__ Km,
    __half* __restrict__ P, float2* __restrict__ stats)
{
    extern __shared__ uint32_t sm[];
    const uint32_t sbase = smem_u32(sm);
    const int tid = threadIdx.x, wid = tid >> 5, lane = tid & 31;
    const int bm = blockIdx.y * 128, bn = blockIdx.x * 128;
    const int bz = blockIdx.z;
    const int K = D_DIM;

    const __half* Ag = Qm + (long long)bz * S_LEN * D_DIM + (long long)bm * K;
    const __half* Bg = Km + (long long)bz * S_LEN * D_DIM + (long long)bn * K;

    float acc[4][4][4];
    #pragma unroll
    for (int m = 0; m < 4; m++)
        #pragma unroll
        for (int n = 0; n < 4; n++)
            #pragma unroll
            for (int e = 0; e < 4; e++) acc[m][n][e] = 0.0f;

    gemm_mainloop<0>(Ag, Bg, K, K, sbase, tid, acc);

    __syncthreads();
    float* redM = (float*)sm;              // [4][128]
    float* redS = redM + 512;              // [4][128]

    const int warpM = (wid >> 2) * 64, warpN = (wid & 3) * 32;
    const int r = lane >> 2, q = lane & 3;
    const int wg = wid & 3;

    #pragma unroll
    for (int mt = 0; mt < 4; mt++)
        #pragma unroll
        for (int nt = 0; nt < 4; nt++)
            #pragma unroll
            for (int e = 0; e < 4; e++) acc[mt][nt][e] *= 0.03125f;

    // warp-local row max over 8 cols, reduce over q-lanes
    #pragma unroll
    for (int mt = 0; mt < 4; mt++) {
        #pragma unroll
        for (int rr = 0; rr < 2; rr++) {
            float m = -1e30f;
            #pragma unroll
            for (int nt = 0; nt < 4; nt++) {
                m = fmaxf(m, acc[mt][nt][rr * 2 + 0]);
                m = fmaxf(m, acc[mt][nt][rr * 2 + 1]);
            }
            m = fmaxf(m, __shfl_xor_sync(0xFFFFFFFFu, m, 1));
            m = fmaxf(m, __shfl_xor_sync(0xFFFFFFFFu, m, 2));
            if (q == 0) redM[wg * 128 + warpM + mt * 16 + rr * 8 + r] = m;
        }
    }
    __syncthreads();

    uint32_t* Pout = (uint32_t*)(P + (long long)bz * S_LEN * S_LEN);
    #pragma unroll
    for (int mt = 0; mt < 4; mt++) {
        #pragma unroll
        for (int rr = 0; rr < 2; rr++) {
            int rowL = warpM + mt * 16 + rr * 8 + r;
            float mrow = fmaxf(fmaxf(redM[rowL], redM[128 + rowL]),
                               fmaxf(redM[256 + rowL], redM[384 + rowL]));
            float sum = 0.0f;
            #pragma unroll
            for (int nt = 0; nt < 4; nt++) {
                float p0 = expf(acc[mt][nt][rr * 2 + 0] - mrow);
                float p1 = expf(acc[mt][nt][rr * 2 + 1] - mrow);
                sum += p0 + p1;
                int col = bn + warpN + nt * 8 + q * 2;
                Pout[((long long)(bm + rowL) * S_LEN + col) >> 1] = pack_h2(p0, p1);
            }
            sum += __shfl_xor_sync(0xFFFFFFFFu, sum, 1);
            sum += __shfl_xor_sync(0xFFFFFFFFu, sum, 2);
            if (q == 0) redS[wg * 128 + rowL] = sum;
        }
    }
    __syncthreads();

    if (wg == 0 && q == 0) {
        #pragma unroll
        for (int mt = 0; mt < 4; mt++) {
            #pragma unroll
            for (int rr = 0; rr < 2; rr++) {
                int rowL = warpM + mt * 16 + rr * 8 + r;
                float mrow = fmaxf(fmaxf(redM[rowL], redM[128 + rowL]),
                                   fmaxf(redM[256 + rowL], redM[384 + rowL]));
                float srow = redS[rowL] + redS[128 + rowL] + redS[256 + rowL] + redS[384 + rowL];
                stats[(long long)(bz * S_LEN + bm + rowL) * NTILES + blockIdx.x] =
                    make_float2(mrow, srow);
            }
        }
    }
}

// ======================= rescale: P16 *= exp(m_t - m) / S (in place, inline combine) =======================
__global__ void __launch_bounds__(256) rescale_kernel(
    __half* __restrict__ P16, const float2* __restrict__ stats)
{
    const long long row = blockIdx.x;                 // global q-row 0..8191
    uint2* rp = (uint2*)(P16 + row * S_LEN);          // 256 uint2 x 2 groups (4 halves each)
    const float2* st = stats + row * NTILES;

    float2 s[NTILES];
    float m = -1e30f;
    #pragma unroll
    for (int t = 0; t < NTILES; t++) { s[t] = st[t]; m = fmaxf(m, s[t].x); }
    float S = 0.0f;
    #pragma unroll
    for (int t = 0; t < NTILES; t++) S += s[t].y * expf(s[t].x - m);
    float inv = 1.0f / S;

    const int tid = threadIdx.x;
    #pragma unroll
    for (int g = 0; g < 2; g++) {
        int idx = tid + g * 256;                      // uint2 index; cols 4*idx..4*idx+3
        int t = idx >> 5;                             // tile = (4*idx)/128
        float sc = expf(s[t].x - m) * inv;
        uint2 v = rp[idx];
        __half2 h0 = *(__half2*)&v.x, h1 = *(__half2*)&v.y;
        float2 f0 = __half22float2(h0), f1 = __half22float2(h1);
        v.x = pack_h2(f0.x * sc, f0.y * sc);
        v.y = pack_h2(f1.x * sc, f1.y * sc);
        rp[idx] = v;
    }
}

// ======================= fused projection: QKV + bias + RoPE -> fp16 =======================
__global__ void __launch_bounds__(256, 2) gemm_proj(
    const __half* __restrict__ A, const __half* __restrict__ B,
    const float* __restrict__ bq, const float* __restrict__ bk, const float* __restrict__ bv,
    __half* __restrict__ Q, __half* __restrict__ Kd, __half* __restrict__ V)
{
    extern __shared__ uint32_t sm[];
    const uint32_t sbase = smem_u32(sm);
    const int tid = threadIdx.x, wid = tid >> 5, lane = tid & 31;
    const int bm = blockIdx.y * 128, bn = blockIdx.x * 128;
    const int K = D_DIM;

    const __half* Ag = A + (long long)bm * K;
    const __half* Bg = B + (long long)bn * K;

    float acc[4][4][4];
    #pragma unroll
    for (int m = 0; m < 4; m++)
        #pragma unroll
        for (int n = 0; n < 4; n++)
            #pragma unroll
            for (int e = 0; e < 4; e++) acc[m][n][e] = 0.0f;

    gemm_mainloop<0>(Ag, Bg, K, K, sbase, tid, acc);

    const int warpM = (wid >> 2) * 64, warpN = (wid & 3) * 32;
    const int r = lane >> 2, q = lane & 3;
    const int sel = bn >> 10;                   // 0=Q 1=K 2=V
    const float* bias = (sel == 0) ? bq : (sel == 1) ? bk : bv;
    uint32_t* O = (uint32_t*)((sel == 0) ? Q : (sel == 1) ? Kd : V);

    #pragma unroll
    for (int nt = 0; nt < 4; nt++) {
        int col = bn + warpN + nt * 8 + q * 2;
        int cl  = col & 1023;
        float b0 = bias[cl], b1 = bias[cl + 1];
        float invf = (sel < 2) ? powf(10000.0f, -(float)cl * (1.0f / (float)D_DIM)) : 0.0f;
        #pragma unroll
        for (int mt = 0; mt < 4; mt++) {
            #pragma unroll
            for (int rr = 0; rr < 2; rr++) {
                int row = bm + warpM + mt * 16 + r + rr * 8;
                float v0 = acc[mt][nt][rr * 2 + 0] + b0;
                float v1 = acc[mt][nt][rr * 2 + 1] + b1;
                if (sel < 2) {
                    int s = row & (S_LEN - 1);
                    float sn, cs;
                    sincosf((float)s * invf, &sn, &cs);
                    float t0 = v0 * cs - v1 * sn;
                    float t1 = v0 * sn + v1 * cs;
                    v0 = t0; v1 = t1;
                }
                O[(long long)row * (D_DIM / 2) + (cl >> 1)] = pack_h2(v0, v1);
            }
        }
    }
}

// ---------------- merged fp32 -> fp16 conversion (x + 3 weights, one launch, 16 elems/thread) ----------------
#define XN16 (M_ROWS * D_DIM / 16)
#define WN16 (D_DIM * D_DIM / 16)
__global__ void __launch_bounds__(256) cvt_all_kernel(
    const float* __restrict__ x, const float* __restrict__ wq,
    const float* __restrict__ wk, const float* __restrict__ wv,
    __half* __restrict__ X, __half* __restrict__ W)
{
    int i = blockIdx.x * 256 + threadIdx.x;
    const float* src;
    __half* dst;
    int off;
    if (i < XN16)                { src = x;  dst = X; off = i; }
    else if (i < XN16 + WN16)    { src = wq; dst = W;                     off = i - XN16; }
    else if (i < XN16 + 2*WN16)  { src = wk; dst = W + (size_t)16 * WN16; off = i - XN16 - WN16; }
    else if (i < XN16 + 3*WN16)  { src = wv; dst = W + (size_t)32 * WN16; off = i - XN16 - 2 * WN16; }
    else return;

    const float4* in4 = (const float4*)src;
    #pragma unroll
    for (int h = 0; h < 2; h++) {
        float4 v0 = in4[4 * off + 2 * h], v1 = in4[4 * off + 2 * h + 1];
        uint4 o;
        o.x = pack_h2(v0.x, v0.y);
        o.y = pack_h2(v0.z, v0.w);
        o.z = pack_h2(v1.x, v1.y);
        o.w = pack_h2(v1.z, v1.w);
        ((uint4*)dst)[2 * off + h] = o;
    }
}

// ---------------- launch ----------------
extern "C" void kernel_launch(void* const* d_in, const int* in_sizes, int n_in,
                              void* d_out, int out_size)
{
    const float* x  = (const float*)d_in[0];
    const float* wq = (const float*)d_in[1];
    const float* bq = (const float*)d_in[2];
    const float* wk = (const float*)d_in[3];
    const float* bk = (const float*)d_in[4];
    const float* wv = (const float*)d_in[5];
    const float* bv = (const float*)d_in[6];
    float* out = (float*)d_out;

    __half *X, *W, *Q, *K, *V, *P16;
    float2* stats;
    cudaGetSymbolAddress((void**)&X,     g_X16);
    cudaGetSymbolAddress((void**)&W,     g_W16);
    cudaGetSymbolAddress((void**)&Q,     g_Q16);
    cudaGetSymbolAddress((void**)&K,     g_K16);
    cudaGetSymbolAddress((void**)&V,     g_V16);
    cudaGetSymbolAddress((void**)&P16,   g_P16);
    cudaGetSymbolAddress((void**)&stats, g_stats);

    cudaFuncSetAttribute(gemm_proj,   cudaFuncAttributeMaxDynamicSharedMemorySize, SMEM_GEMM_BYTES);
    cudaFuncSetAttribute(gemm_scores, cudaFuncAttributeMaxDynamicSharedMemorySize, SMEM_GEMM_BYTES);
    cudaFuncSetAttribute(gemm_pv,     cudaFuncAttributeMaxDynamicSharedMemorySize, SMEM_GEMM_BYTES);

    // 0) merged fp32 -> fp16 conversions (x + wq|wk|wv), one launch
    {
        int total = XN16 + 3 * WN16;
        cvt_all_kernel<<<(total + 255) / 256, 256>>>(x, wq, wk, wv, X, W);
    }

    // 1) fused QKV projection + bias + RoPE (M=8192, N=3072, K=1024)
    dim3 gP(3 * D_DIM / 128, M_ROWS / 128, 1);
    gemm_proj<<<gP, 256, SMEM_GEMM_BYTES>>>(X, W, bq, bk, bv, Q, K, V);

    // 2) scores + per-tile exp/stats -> P16 (M=2048, N=2048, K=1024), batched
    dim3 gS(S_LEN / 128, S_LEN / 128, B_SZ);
    gemm_scores<<<gS, 256, SMEM_GEMM_BYTES>>>(Q, K, P16, stats);

    // 3) rescale P16 in place (inline per-row combine of tile stats)
    rescale_kernel<<<M_ROWS, 256>>>(P16, stats);

    // 4) out = P @ V (V row-major [s][d], NN via ldmatrix.trans), batched
    dim3 gO(D_DIM / 128, S_LEN / 128, B_SZ);
    gemm_pv<<<gO, 256, SMEM_GEMM_BYTES>>>(P16, V, out, D_DIM, S_LEN,
                                          (long long)S_LEN * S_LEN, (long long)S_LEN * D_DIM,
                                          (long long)S_LEN * D_DIM);
}

// round 17
// speedup vs baseline: 1.0746x; 1.0746x over previous
#include <cuda_runtime.h>
#include <cuda_fp16.h>
#include <math.h>
#include <stdint.h>

#define B_SZ  4
#define S_LEN 2048
#define D_DIM 1024
#define M_ROWS (B_SZ * S_LEN)   // 8192
#define NTILES (S_LEN / 128)    // 16

// ---------------- scratch (allocation-free: __device__ globals) ----------------
__device__ __half g_X16[(size_t)M_ROWS * D_DIM];              // fp16(x)
__device__ __half g_W16[(size_t)3 * D_DIM * D_DIM];           // fp16(wq|wk|wv) [3072][1024]
__device__ __half g_Q16[(size_t)M_ROWS * D_DIM];              // fp16 post-rope
__device__ __half g_K16[(size_t)M_ROWS * D_DIM];
__device__ __half g_V16[(size_t)M_ROWS * D_DIM];              // row-major [b*S+s][d]
__device__ __half g_P16[(size_t)B_SZ * S_LEN * S_LEN];        // fp16 exp(s)
__device__ float  g_tsum[(size_t)M_ROWS * NTILES];            // per (qrow, ktile) partial sum
__device__ float  g_rinv[(size_t)M_ROWS];                     // 1 / rowsum

// ======================= helpers =======================
__device__ __forceinline__ uint32_t smem_u32(const void* p) {
    uint32_t a;
    asm("{ .reg .u64 t; cvta.to.shared.u64 t, %1; cvt.u32.u64 %0, t; }" : "=r"(a) : "l"(p));
    return a;
}
__device__ __forceinline__ uint32_t pack_h2(float a, float b) {
    __half2 h = __floats2half2_rn(a, b);
    return *(uint32_t*)&h;
}
__device__ __forceinline__ void ldsm4(uint32_t& r0, uint32_t& r1, uint32_t& r2, uint32_t& r3,
                                      uint32_t addr) {
    asm volatile("ldmatrix.sync.aligned.m8n8.x4.shared.b16 {%0,%1,%2,%3}, [%4];"
                 : "=r"(r0), "=r"(r1), "=r"(r2), "=r"(r3) : "r"(addr));
}
__device__ __forceinline__ void ldsm4t(uint32_t& r0, uint32_t& r1, uint32_t& r2, uint32_t& r3,
                                       uint32_t addr) {
    asm volatile("ldmatrix.sync.aligned.m8n8.x4.trans.shared.b16 {%0,%1,%2,%3}, [%4];"
                 : "=r"(r0), "=r"(r1), "=r"(r2), "=r"(r3) : "r"(addr));
}
__device__ __forceinline__ void mma16816(float& d0, float& d1, float& d2, float& d3,
                                         uint32_t a0, uint32_t a1, uint32_t a2, uint32_t a3,
                                         uint32_t b0, uint32_t b1) {
    asm volatile(
        "mma.sync.aligned.m16n8k16.row.col.f32.f16.f16.f32 "
        "{%0,%1,%2,%3},{%4,%5,%6,%7},{%8,%9},{%0,%1,%2,%3};"
        : "+f"(d0), "+f"(d1), "+f"(d2), "+f"(d3)
        : "r"(a0), "r"(a1), "r"(a2), "r"(a3), "r"(b0), "r"(b1));
}
__device__ __forceinline__ void cp16(uint32_t dst, const void* src) {
    asm volatile("cp.async.cg.shared.global [%0], [%1], 16;"
                 :: "r"(dst), "l"(__cvta_generic_to_global(src)) : "memory");
}
#define CP_COMMIT() asm volatile("cp.async.commit_group;" ::: "memory")
#define CP_WAIT2()  asm volatile("cp.async.wait_group 2;" ::: "memory")

// A / NT-B tiles: [128 rows][64 fp16] = 128B rows, 8x 16B chunks; phys chunk = ch ^ (row&7)
__device__ __forceinline__ uint32_t swp(int row, int chunk) {
    return (uint32_t)(row * 128 + ((chunk ^ (row & 7)) << 4));
}
// NN-B tile: [64 k-rows][128 n-cols] fp16 = 256B rows; chunk c(0..15) ^= k&7
__device__ __forceinline__ uint32_t swb(int k, int chunk) {
    return (uint32_t)(k * 256 + ((chunk ^ (k & 7)) << 4));
}

// CTA tile 128x128, BK=64, 8 warps (2x4), warp tile 64x32, 2 CTAs/SM
#define TILE_HB 16384
#define STAGE_BYTES (2 * TILE_HB)
#define SMEM_GEMM_BYTES (3 * STAGE_BYTES)   // 98304

// ======================= shared mainloop (round-11 proven: two-sync, WAIT2) =======================
template<int BMODE>
__device__ __forceinline__ void issue_stage(
    uint32_t base, const __half* Ag, const __half* Bg, int K, int ldB, int tid, int c)
{
    const __half* Ac = Ag + (long long)c * 64;
    #pragma unroll
    for (int p = 0; p < 4; p++) {
        int cidx = tid + p * 256;
        int row = cidx >> 3, ch = cidx & 7;
        cp16(base + swp(row, ch), Ac + (long long)row * K + ch * 8);
    }
    if (BMODE == 0) {
        const __half* Bc = Bg + (long long)c * 64;
        #pragma unroll
        for (int p = 0; p < 4; p++) {
            int cidx = tid + p * 256;
            int row = cidx >> 3, ch = cidx & 7;
            cp16(base + TILE_HB + swp(row, ch), Bc + (long long)row * K + ch * 8);
        }
    } else {
        const __half* Bc = Bg + (long long)c * 64 * ldB;
        #pragma unroll
        for (int p = 0; p < 4; p++) {
            int cidx = tid + p * 256;
            int k = cidx >> 4, ch = cidx & 15;
            cp16(base + TILE_HB + swb(k, ch), Bc + (long long)k * ldB + ch * 8);
        }
    }
    CP_COMMIT();
}

template<int BMODE>
__device__ __forceinline__ void gemm_mainloop(
    const __half* Ag, const __half* Bg, int K, int ldB,
    uint32_t sbase, int tid, float acc[4][4][4])
{
    const int wid = tid >> 5, lane = tid & 31;
    const int warpM = (wid >> 2) * 64, warpN = (wid & 3) * 32;
    const int NC = K >> 6;

    issue_stage<BMODE>(sbase,               Ag, Bg, K, ldB, tid, 0);
    issue_stage<BMODE>(sbase + STAGE_BYTES, Ag, Bg, K, ldB, tid, 1);

    const int laA = lane & 15, lcA = lane >> 4;
    const int laB = (lane & 7) + ((lane & 16) >> 1);
    const int lcB = (lane >> 3) & 1;
    const int lrT = lane & 7, gT = lane >> 3;

    for (int c = 0; c < NC; c++) {
        if (c + 2 < NC) {
            issue_stage<BMODE>(sbase + ((c + 2) % 3) * STAGE_BYTES, Ag, Bg, K, ldB, tid, c + 2);
        } else {
            CP_COMMIT();
        }
        CP_WAIT2();
        __syncthreads();

        const uint32_t sA = sbase + (c % 3) * STAGE_BYTES;
        const uint32_t sB = sA + TILE_HB;

        #pragma unroll
        for (int kk = 0; kk < 4; kk++) {
            uint32_t b[4][2];
            if (BMODE == 0) {
                #pragma unroll
                for (int g = 0; g < 2; g++) {
                    int rB = warpN + g * 16 + laB;
                    uint32_t off = swp(rB, 2 * kk + lcB);
                    ldsm4(b[2*g][0], b[2*g][1], b[2*g+1][0], b[2*g+1][1], sB + off);
                }
            } else {
                int k = kk * 16 + (gT & 1) * 8 + lrT;
                int cb = (warpN >> 3) + (gT >> 1);
                ldsm4t(b[0][0], b[0][1], b[1][0], b[1][1], sB + swb(k, cb));
                ldsm4t(b[2][0], b[2][1], b[3][0], b[3][1], sB + swb(k, cb + 2));
            }
            #pragma unroll
            for (int mt = 0; mt < 4; mt++) {
                int rA = warpM + mt * 16 + laA;
                uint32_t off = swp(rA, 2 * kk + lcA);
                uint32_t a0, a1, a2, a3;
                ldsm4(a0, a1, a2, a3, sA + off);
                #pragma unroll
                for (int nt = 0; nt < 4; nt++)
                    mma16816(acc[mt][nt][0], acc[mt][nt][1], acc[mt][nt][2], acc[mt][nt][3],
                             a0, a1, a2, a3, b[nt][0], b[nt][1]);
            }
        }
        __syncthreads();
    }
}

// ======================= scores GEMM: store exp(s) fp16 + per-tile row sums =======================
__global__ void __launch_bounds__(256, 2) gemm_scores(
    const __half* __restrict__ Qm, const __half* __restrict__ Km,
    __half* __restrict__ P, float* __restrict__ tsum)
{
    extern __shared__ uint32_t sm[];
    const uint32_t sbase = smem_u32(sm);
    const int tid = threadIdx.x, wid = tid >> 5, lane = tid & 31;
    const int bm = blockIdx.y * 128, bn = blockIdx.x * 128;
    const int bz = blockIdx.z;
    const int K = D_DIM;

    const __half* Ag = Qm + (long long)bz * S_LEN * D_DIM + (long long)bm * K;
    const __half* Bg = Km + (long long)bz * S_LEN * D_DIM + (long long)bn * K;

    float acc[4][4][4];
    #pragma unroll
    for (int m = 0; m < 4; m++)
        #pragma unroll
        for (int n = 0; n < 4; n++)
            #pragma unroll
            for (int e = 0; e < 4; e++) acc[m][n][e] = 0.0f;

    gemm_mainloop<0>(Ag, Bg, K, K, sbase, tid, acc);

    __syncthreads();                       // before reusing smem for reduction
    float* redS = (float*)sm;              // [4][128]

    const int warpM = (wid >> 2) * 64, warpN = (wid & 3) * 32;
    const int r = lane >> 2, q = lane & 3;
    const int wg = wid & 3;

    // exp(alpha * s) in place
    #pragma unroll
    for (int mt = 0; mt < 4; mt++)
        #pragma unroll
        for (int nt = 0; nt < 4; nt++)
            #pragma unroll
            for (int e = 0; e < 4; e++) acc[mt][nt][e] = expf(acc[mt][nt][e] * 0.03125f);

    // store P16 + per-row partial sums
    uint32_t* Pout = (uint32_t*)(P + (long long)bz * S_LEN * S_LEN);
    #pragma unroll
    for (int mt = 0; mt < 4; mt++) {
        #pragma unroll
        for (int rr = 0; rr < 2; rr++) {
            int rowL = warpM + mt * 16 + rr * 8 + r;
            float sum = 0.0f;
            #pragma unroll
            for (int nt = 0; nt < 4; nt++) {
                float p0 = acc[mt][nt][rr * 2 + 0];
                float p1 = acc[mt][nt][rr * 2 + 1];
                sum += p0 + p1;
                int col = bn + warpN + nt * 8 + q * 2;
                Pout[((long long)(bm + rowL) * S_LEN + col) >> 1] = pack_h2(p0, p1);
            }
            sum += __shfl_xor_sync(0xFFFFFFFFu, sum, 1);
            sum += __shfl_xor_sync(0xFFFFFFFFu, sum, 2);
            if (q == 0) redS[wg * 128 + rowL] = sum;
        }
    }
    __syncthreads();

    if (wg == 0 && q == 0) {
        #pragma unroll
        for (int mt = 0; mt < 4; mt++) {
            #pragma unroll
            for (int rr = 0; rr < 2; rr++) {
                int rowL = warpM + mt * 16 + rr * 8 + r;
                float srow = redS[rowL] + redS[128 + rowL] + redS[256 + rowL] + redS[384 + rowL];
                tsum[(long long)(bz * S_LEN + bm + rowL) * NTILES + blockIdx.x] = srow;
            }
        }
    }
}

// ======================= rowsum: one warp per row -> rinv = 1/S =======================
__global__ void __launch_bounds__(256) rowsum_kernel(
    const float* __restrict__ tsum, float* __restrict__ rinv)
{
    int w = (blockIdx.x * 256 + threadIdx.x) >> 5;   // row 0..8191 (grid = 1024 blocks)
    int lane = threadIdx.x & 31;
    float v = (lane < NTILES) ? tsum[(long long)w * NTILES + lane] : 0.0f;
    #pragma unroll
    for (int o = 8; o > 0; o >>= 1) v += __shfl_xor_sync(0xFFFFFFFFu, v, o);
    if (lane == 0) rinv[w] = 1.0f / v;
}

// ======================= PV GEMM (NN via ldmatrix.trans) + row normalize =======================
__global__ void __launch_bounds__(256, 2) gemm_pv(
    const __half* __restrict__ P, const __half* __restrict__ V,
    const float* __restrict__ rinv, float* __restrict__ out)
{
    extern __shared__ uint32_t sm[];
    const uint32_t sbase = smem_u32(sm);
    const int tid = threadIdx.x, wid = tid >> 5, lane = tid & 31;
    const int bm = blockIdx.y * 128, bn = blockIdx.x * 128;
    const int bz = blockIdx.z;
    const int K = S_LEN, N = D_DIM;

    const __half* Ag = P + (long long)bz * S_LEN * S_LEN + (long long)bm * K;
    const __half* Bg = V + (long long)bz * S_LEN * D_DIM + bn;

    float acc[4][4][4];
    #pragma unroll
    for (int m = 0; m < 4; m++)
        #pragma unroll
        for (int n = 0; n < 4; n++)
            #pragma unroll
            for (int e = 0; e < 4; e++) acc[m][n][e] = 0.0f;

    gemm_mainloop<1>(Ag, Bg, K, N, sbase, tid, acc);

    float* C = out + (long long)bz * S_LEN * D_DIM;
    const float* ri = rinv + (long long)bz * S_LEN + bm;
    const int warpM = (wid >> 2) * 64, warpN = (wid & 3) * 32;
    const int r = lane >> 2, q = lane & 3;
    #pragma unroll
    for (int mt = 0; mt < 4; mt++) {
        int rowL = warpM + mt * 16 + r;
        float s0 = ri[rowL], s1 = ri[rowL + 8];
        #pragma unroll
        for (int nt = 0; nt < 4; nt++) {
            int col = bn + warpN + nt * 8 + q * 2;
            *(float2*)(C + (long long)(bm + rowL) * N + col) =
                make_float2(acc[mt][nt][0] * s0, acc[mt][nt][1] * s0);
            *(float2*)(C + (long long)(bm + rowL + 8) * N + col) =
                make_float2(acc[mt][nt][2] * s1, acc[mt][nt][3] * s1);
        }
    }
}

// ======================= fused projection: QKV + bias + RoPE -> fp16 =======================
__global__ void __launch_bounds__(256, 2) gemm_proj(
    const __half* __restrict__ A, const __half* __restrict__ B,
    const float* __restrict__ bq, const float* __restrict__ bk, const float* __restrict__ bv,
    __half* __restrict__ Q, __half* __restrict__ Kd, __half* __restrict__ V)
{
    extern __shared__ uint32_t sm[];
    const uint32_t sbase = smem_u32(sm);
    const int tid = threadIdx.x, wid = tid >> 5, lane = tid & 31;
    const int bm = blockIdx.y * 128, bn = blockIdx.x * 128;
    const int K = D_DIM;

    const __half* Ag = A + (long long)bm * K;
    const __half* Bg = B + (long long)bn * K;

    float acc[4][4][4];
    #pragma unroll
    for (int m = 0; m < 4; m++)
        #pragma unroll
        for (int n = 0; n < 4; n++)
            #pragma unroll
            for (int e = 0; e < 4; e++) acc[m][n][e] = 0.0f;

    gemm_mainloop<0>(Ag, Bg, K, K, sbase, tid, acc);

    const int warpM = (wid >> 2) * 64, warpN = (wid & 3) * 32;
    const int r = lane >> 2, q = lane & 3;
    const int sel = bn >> 10;                   // 0=Q 1=K 2=V
    const float* bias = (sel == 0) ? bq : (sel == 1) ? bk : bv;
    uint32_t* O = (uint32_t*)((sel == 0) ? Q : (sel == 1) ? Kd : V);

    #pragma unroll
    for (int nt = 0; nt < 4; nt++) {
        int col = bn + warpN + nt * 8 + q * 2;
        int cl  = col & 1023;
        float b0 = bias[cl], b1 = bias[cl + 1];
        float invf = (sel < 2) ? powf(10000.0f, -(float)cl * (1.0f / (float)D_DIM)) : 0.0f;
        #pragma unroll
        for (int mt = 0; mt < 4; mt++) {
            #pragma unroll
            for (int rr = 0; rr < 2; rr++) {
                int row = bm + warpM + mt * 16 + r + rr * 8;
                float v0 = acc[mt][nt][rr * 2 + 0] + b0;
                float v1 = acc[mt][nt][rr * 2 + 1] + b1;
                if (sel < 2) {
                    int s = row & (S_LEN - 1);
                    float sn, cs;
                    sincosf((float)s * invf, &sn, &cs);
                    float t0 = v0 * cs - v1 * sn;
                    float t1 = v0 * sn + v1 * cs;
                    v0 = t0; v1 = t1;
                }
                O[(long long)row * (D_DIM / 2) + (cl >> 1)] = pack_h2(v0, v1);
            }
        }
    }
}

// ---------------- merged fp32 -> fp16 conversion (x + 3 weights, one launch, 16 elems/thread) ----------------
#define XN16 (M_ROWS * D_DIM / 16)
#define WN16 (D_DIM * D_DIM / 16)
__global__ void __launch_bounds__(256) cvt_all_kernel(
    const float* __restrict__ x, const float* __restrict__ wq,
    const float* __restrict__ wk, const float* __restrict__ wv,
    __half* __restrict__ X, __half* __restrict__ W)
{
    int i = blockIdx.x * 256 + threadIdx.x;
    const float* src;
    __half* dst;
    int off;
    if (i < XN16)                { src = x;  dst = X; off = i; }
    else if (i < XN16 + WN16)    { src = wq; dst = W;                     off = i - XN16; }
    else if (i < XN16 + 2*WN16)  { src = wk; dst = W + (size_t)16 * WN16; off = i - XN16 - WN16; }
    else if (i < XN16 + 3*WN16)  { src = wv; dst = W + (size_t)32 * WN16; off = i - XN16 - 2 * WN16; }
    else return;

    const float4* in4 = (const float4*)src;
    #pragma unroll
    for (int h = 0; h < 2; h++) {
        float4 v0 = in4[4 * off + 2 * h], v1 = in4[4 * off + 2 * h + 1];
        uint4 o;
        o.x = pack_h2(v0.x, v0.y);
        o.y = pack_h2(v0.z, v0.w);
        o.z = pack_h2(v1.x, v1.y);
        o.w = pack_h2(v1.z, v1.w);
        ((uint4*)dst)[2 * off + h] = o;
    }
}

// ---------------- launch ----------------
extern "C" void kernel_launch(void* const* d_in, const int* in_sizes, int n_in,
                              void* d_out, int out_size)
{
    const float* x  = (const float*)d_in[0];
    const float* wq = (const float*)d_in[1];
    const float* bq = (const float*)d_in[2];
    const float* wk = (const float*)d_in[3];
    const float* bk = (const float*)d_in[4];
    const float* wv = (const float*)d_in[5];
    const float* bv = (const float*)d_in[6];
    float* out = (float*)d_out;

    __half *X, *W, *Q, *K, *V, *P16;
    float *tsum, *rinv;
    cudaGetSymbolAddress((void**)&X,    g_X16);
    cudaGetSymbolAddress((void**)&W,    g_W16);
    cudaGetSymbolAddress((void**)&Q,    g_Q16);
    cudaGetSymbolAddress((void**)&K,    g_K16);
    cudaGetSymbolAddress((void**)&V,    g_V16);
    cudaGetSymbolAddress((void**)&P16,  g_P16);
    cudaGetSymbolAddress((void**)&tsum, g_tsum);
    cudaGetSymbolAddress((void**)&rinv, g_rinv);

    cudaFuncSetAttribute(gemm_proj,   cudaFuncAttributeMaxDynamicSharedMemorySize, SMEM_GEMM_BYTES);
    cudaFuncSetAttribute(gemm_scores, cudaFuncAttributeMaxDynamicSharedMemorySize, SMEM_GEMM_BYTES);
    cudaFuncSetAttribute(gemm_pv,     cudaFuncAttributeMaxDynamicSharedMemorySize, SMEM_GEMM_BYTES);

    // 0) merged fp32 -> fp16 conversions (x + wq|wk|wv), one launch
    {
        int total = XN16 + 3 * WN16;
        cvt_all_kernel<<<(total + 255) / 256, 256>>>(x, wq, wk, wv, X, W);
    }

    // 1) fused QKV projection + bias + RoPE (M=8192, N=3072, K=1024)
    dim3 gP(3 * D_DIM / 128, M_ROWS / 128, 1);
    gemm_proj<<<gP, 256, SMEM_GEMM_BYTES>>>(X, W, bq, bk, bv, Q, K, V);

    // 2) scores -> P16 = exp(s) + per-tile row sums (M=2048, N=2048, K=1024), batched
    dim3 gS(S_LEN / 128, S_LEN / 128, B_SZ);
    gemm_scores<<<gS, 256, SMEM_GEMM_BYTES>>>(Q, K, P16, tsum);

    // 3) rowsum: 1 warp per row -> rinv
    rowsum_kernel<<<M_ROWS / 8, 256>>>(tsum, rinv);

    // 4) out = (P @ V) * rinv[row] (NN via ldmatrix.trans), batched
    dim3 gO(D_DIM / 128, S_LEN / 128, B_SZ);
    gemm_pv<<<gO, 256, SMEM_GEMM_BYTES>>>(P16, V, rinv, out);
}